// round 14
// baseline (speedup 1.0000x reference)
#include <cuda_runtime.h>
#include <cuda_fp16.h>
#include <cstdint>

// ---------------- problem constants ----------------
#define T_LEN   2048
#define BATCH   2
#define D_MODEL 512
#define S_WIN   32
#define M_ROWS  4096           // T*B
#define NCH     1024           // B*D channels

// ---------------- scratch (no allocation allowed) ----------------
__device__ float  g_k [M_ROWS * D_MODEL];          // k projection (fp32: exp-sensitive)
__device__ __half g_hq[M_ROWS * D_MODEL];          // q projection (fp16)
__device__ __half g_hv[M_ROWS * D_MODEL];          // v projection (fp16)
__device__ __half g_hek[M_ROWS * D_MODEL];         // exp(k) (fp16)
__device__ __half g_hx[3 * M_ROWS * D_MODEL];      // fp16 rounded query,key,value
__device__ __half g_hw[4 * D_MODEL * D_MODEL];     // fp16 rounded Wq,Wk,Wv,Wo
__device__ __half g_hy[M_ROWS * D_MODEL];          // fp16 y (gemm_o input)
__device__ float g_epb[T_LEN * S_WIN];

#define NCHUNK 64
#define CHLEN  32
__device__ float g_pnum[NCH * NCHUNK];   // raw partials, [ch][chunk]
__device__ float g_pden[NCH * NCHUNK];
__device__ float g_pren[NCHUNK * NCH];   // exclusive prefix, [chunk][ch]
__device__ float g_pred[NCHUNK * NCH];

// grid-barrier state (self-resetting; zero-initialized at module load)
__device__ unsigned g_ctr0 = 0, g_flag0 = 0;
__device__ unsigned g_ctr1 = 0, g_flag1 = 0;
__device__ unsigned g_done = 0;

// ---------------- helpers ----------------
__device__ __forceinline__ void mma16(float c[4], const uint32_t a[4], const uint32_t b[2]) {
    asm volatile(
        "mma.sync.aligned.m16n8k16.row.col.f32.f16.f16.f32 "
        "{%0,%1,%2,%3}, {%4,%5,%6,%7}, {%8,%9}, {%0,%1,%2,%3};\n"
        : "+f"(c[0]), "+f"(c[1]), "+f"(c[2]), "+f"(c[3])
        : "r"(a[0]), "r"(a[1]), "r"(a[2]), "r"(a[3]),
          "r"(b[0]), "r"(b[1]));
}
__device__ __forceinline__ void ldsm_x4(uint32_t r[4], uint32_t addr) {
    asm volatile("ldmatrix.sync.aligned.m8n8.x4.shared.b16 {%0,%1,%2,%3}, [%4];"
        : "=r"(r[0]), "=r"(r[1]), "=r"(r[2]), "=r"(r[3]) : "r"(addr));
}
__device__ __forceinline__ void cp16(uint32_t dst, const void* src) {
    asm volatile("cp.async.cg.shared.global [%0], [%1], 16;" :: "r"(dst), "l"(src));
}
__device__ __forceinline__ void cp_commit() {
    asm volatile("cp.async.commit_group;" ::: "memory");
}
__device__ __forceinline__ uint32_t smem_to_u32(const void* p) {
    uint32_t a;
    asm("{ .reg .u64 t; cvta.to.shared.u64 t, %1; cvt.u32.u64 %0, t; }" : "=r"(a) : "l"(p));
    return a;
}
__device__ __forceinline__ uint32_t pack_h2(float a, float b) {
    __half2 h = __floats2half2_rn(a, b);
    return *reinterpret_cast<uint32_t*>(&h);
}
// grid barrier: all NBLK blocks arrive, then proceed. Requires full residency.
__device__ __forceinline__ void grid_barrier(unsigned* ctr, unsigned* flag, unsigned nblk) {
    __syncthreads();
    if (threadIdx.x == 0) {
        __threadfence();
        unsigned v = atomicAdd(ctr, 1);
        if (v == nblk - 1) {
            atomicExch(flag, 1u);
        } else {
            while (atomicAdd(flag, 0u) == 0u) __nanosleep(64);
        }
    }
    __syncthreads();
    __threadfence();
}

// ---------------- prep1: fp16 conversion + exp(pb) window table ----------------
__global__ __launch_bounds__(256) void prep1_kernel(
    const float* __restrict__ pb,
    const float* __restrict__ query, const float* __restrict__ key, const float* __restrict__ value,
    const float* __restrict__ Wq, const float* __restrict__ Wk, const float* __restrict__ Wv,
    const float* __restrict__ Wo)
{
    int blk = blockIdx.x;
    if (blk >= 7168) {
        int id = (blk - 7168) * 256 + threadIdx.x;
        int t = id >> 5, j = id & 31;
        int idx = t - (S_WIN - 1) + j;
        g_epb[id] = (idx >= 0) ? __expf(pb[(size_t)t * T_LEN + idx]) : 0.0f;
        return;
    }
    int i = blk * 256 + threadIdx.x;   // float4 index
    const float4* src;
    __half* dstbase;
    int j;
    if (i < 524288)       { src = (const float4*)query; dstbase = g_hx;           j = i; }
    else if (i < 1048576) { src = (const float4*)key;   dstbase = g_hx + 2097152; j = i - 524288; }
    else if (i < 1572864) { src = (const float4*)value; dstbase = g_hx + 4194304; j = i - 1048576; }
    else if (i < 1638400) { src = (const float4*)Wq;    dstbase = g_hw;           j = i - 1572864; }
    else if (i < 1703936) { src = (const float4*)Wk;    dstbase = g_hw + 262144;  j = i - 1638400; }
    else if (i < 1769472) { src = (const float4*)Wv;    dstbase = g_hw + 524288;  j = i - 1703936; }
    else                  { src = (const float4*)Wo;    dstbase = g_hw + 786432;  j = i - 1769472; }
    float4 v = src[j];
    uint2 h;
    h.x = pack_h2(v.x, v.y);
    h.y = pack_h2(v.z, v.w);
    *reinterpret_cast<uint2*>(dstbase + (size_t)j * 4) = h;
}

// ---------------- fp16 pipelined GEMM ----------------
// z=0 -> q as fp16, z=1 -> k as fp32, z=2 -> v as fp16
#define GBM 128
#define GBN 128
#define GBK 64
#define GSTG 3
#define NKT 8
#define PADH 72
#define ROWB 144
#define A_HALVES (GBM * PADH)
#define STG_HALVES (2 * A_HALVES)
#define STG_BYTES (STG_HALVES * 2)
#define GEMM_SMEM (GSTG * STG_BYTES)

__device__ __forceinline__ void ld_stage(uint32_t sb, const __half* __restrict__ A,
                                         const __half* __restrict__ W,
                                         int bm, int bn, int kt, int tid) {
    uint32_t base = sb + (uint32_t)((kt % GSTG) * STG_BYTES);
#pragma unroll
    for (int i = 0; i < 4; i++) {
        int chunk = tid + i * 256;
        int row = chunk >> 3, c16 = chunk & 7;
        cp16(base + (uint32_t)(row * ROWB + c16 * 16),
             &A[(size_t)(bm * GBM + row) * 512 + kt * GBK + c16 * 8]);
    }
    base += A_HALVES * 2;
#pragma unroll
    for (int i = 0; i < 4; i++) {
        int chunk = tid + i * 256;
        int row = chunk >> 3, c16 = chunk & 7;
        cp16(base + (uint32_t)(row * ROWB + c16 * 16),
             &W[(size_t)(bn * GBN + row) * 512 + kt * GBK + c16 * 8]);
    }
    cp_commit();
}

__global__ void __launch_bounds__(256, 2) gemm_qkv(
    const __half* __restrict__ X, const __half* __restrict__ Wh,
    const float* __restrict__ B0, const float* __restrict__ B1, const float* __restrict__ B2,
    __half* __restrict__ Cq, float* __restrict__ Ck, __half* __restrict__ Cv)
{
    extern __shared__ char smem_c[];
    const uint32_t sb = smem_to_u32(smem_c);
    const int tid  = threadIdx.x;
    const int l    = tid & 31;
    const int wid  = tid >> 5;
    const int wm   = wid & 1;
    const int wn   = wid >> 1;
    const int bm   = blockIdx.x, bn = blockIdx.y;
    const int z    = blockIdx.z;

    const __half* A    = X  + (size_t)z * (M_ROWS * D_MODEL);
    const __half* W    = Wh + (size_t)z * (D_MODEL * D_MODEL);
    const float* bias  = (z == 0) ? B0 : (z == 1) ? B1 : B2;

    const uint32_t a_off = (uint32_t)(((l & 7) + ((l >> 3) & 1) * 8) * ROWB + (l >> 4) * 16);
    const uint32_t b_off = (uint32_t)(((l & 7) + (l >> 4) * 8) * ROWB + ((l >> 3) & 1) * 16);

    float acc[4][4][4];
#pragma unroll
    for (int mt = 0; mt < 4; mt++)
#pragma unroll
        for (int nt = 0; nt < 4; nt++)
#pragma unroll
            for (int i = 0; i < 4; i++) acc[mt][nt][i] = 0.0f;

    ld_stage(sb, A, W, bm, bn, 0, tid);
    ld_stage(sb, A, W, bm, bn, 1, tid);

#pragma unroll 1
    for (int kt = 0; kt < NKT; kt++) {
        if (kt < NKT - 2) asm volatile("cp.async.wait_group 1;" ::: "memory");
        else              asm volatile("cp.async.wait_group 0;" ::: "memory");
        __syncthreads();

        if (kt + 2 < NKT) ld_stage(sb, A, W, bm, bn, kt + 2, tid);

        const uint32_t As_u = sb + (uint32_t)((kt % GSTG) * STG_BYTES);
        const uint32_t Bs_u = As_u + A_HALVES * 2;
        const uint32_t a_base = As_u + a_off + (uint32_t)(wm * 64 * ROWB);
        const uint32_t b_base = Bs_u + b_off + (uint32_t)(wn * 32 * ROWB);
#pragma unroll
        for (int ks = 0; ks < 4; ks++) {
            const uint32_t kb = ks * 32;
            uint32_t a[4][4], b[2][4];
#pragma unroll
            for (int mt = 0; mt < 4; mt++)
                ldsm_x4(a[mt], a_base + (uint32_t)(mt * 16 * ROWB) + kb);
            ldsm_x4(b[0], b_base + kb);
            ldsm_x4(b[1], b_base + (uint32_t)(16 * ROWB) + kb);
#pragma unroll
            for (int mt = 0; mt < 4; mt++)
#pragma unroll
                for (int nt = 0; nt < 4; nt++)
                    mma16(acc[mt][nt], a[mt], &b[nt >> 1][(nt & 1) * 2]);
        }
    }

    const int r_fr = l >> 2;
    const int c2 = (l & 3) * 2;
    if (z == 1) {
#pragma unroll
        for (int mt = 0; mt < 4; mt++) {
#pragma unroll
            for (int nt = 0; nt < 4; nt++) {
                int row = bm * GBM + wm * 64 + mt * 16 + r_fr;
                int col = bn * GBN + wn * 32 + nt * 8 + c2;
                float b0 = bias[col], b1 = bias[col + 1];
                *reinterpret_cast<float2*>(&Ck[(size_t)row * 512 + col]) =
                    make_float2(acc[mt][nt][0] + b0, acc[mt][nt][1] + b1);
                *reinterpret_cast<float2*>(&Ck[(size_t)(row + 8) * 512 + col]) =
                    make_float2(acc[mt][nt][2] + b0, acc[mt][nt][3] + b1);
            }
        }
    } else {
        __half* Ch = (z == 0) ? Cq : Cv;
#pragma unroll
        for (int mt = 0; mt < 4; mt++) {
#pragma unroll
            for (int nt = 0; nt < 4; nt++) {
                int row = bm * GBM + wm * 64 + mt * 16 + r_fr;
                int col = bn * GBN + wn * 32 + nt * 8 + c2;
                float b0 = bias[col], b1 = bias[col + 1];
                *reinterpret_cast<__half2*>(&Ch[(size_t)row * 512 + col]) =
                    __floats2half2_rn(acc[mt][nt][0] + b0, acc[mt][nt][1] + b1);
                *reinterpret_cast<__half2*>(&Ch[(size_t)(row + 8) * 512 + col]) =
                    __floats2half2_rn(acc[mt][nt][2] + b0, acc[mt][nt][3] + b1);
            }
        }
    }
}

// ---------------- gemm_o: BM=64, BN=128, 256 threads (8 warps, 32x32 tiles) --------
#define OBM 64
#define OA_HALVES (OBM * PADH)
#define OSTG_HALVES (OA_HALVES + A_HALVES)
#define OSTG_BYTES (OSTG_HALVES * 2)           // 27,648 B
#define OGEMM_SMEM (GSTG * OSTG_BYTES)         // 82,944 B

__device__ __forceinline__ void ld_stage_o(uint32_t sb, const __half* __restrict__ A,
                                           const __half* __restrict__ W,
                                           int bm, int bn, int kt, int tid) {
    uint32_t base = sb + (uint32_t)((kt % GSTG) * OSTG_BYTES);
#pragma unroll
    for (int i = 0; i < 2; i++) {
        int chunk = tid + i * 256;
        int row = chunk >> 3, c16 = chunk & 7;
        cp16(base + (uint32_t)(row * ROWB + c16 * 16),
             &A[(size_t)(bm * OBM + row) * 512 + kt * GBK + c16 * 8]);
    }
    base += OA_HALVES * 2;
#pragma unroll
    for (int i = 0; i < 4; i++) {
        int chunk = tid + i * 256;
        int row = chunk >> 3, c16 = chunk & 7;
        cp16(base + (uint32_t)(row * ROWB + c16 * 16),
             &W[(size_t)(bn * GBN + row) * 512 + kt * GBK + c16 * 8]);
    }
    cp_commit();
}

__global__ void __launch_bounds__(256, 2) gemm_o(
    const __half* __restrict__ A, const __half* __restrict__ W,
    const float* __restrict__ bias, float* __restrict__ C)
{
    extern __shared__ char smem_c[];
    const uint32_t sb = smem_to_u32(smem_c);
    const int tid  = threadIdx.x;
    const int l    = tid & 31;
    const int wid  = tid >> 5;
    const int wm   = wid & 1;
    const int wn   = wid >> 1;
    const int bm   = blockIdx.x, bn = blockIdx.y;

    const uint32_t a_off = (uint32_t)(((l & 7) + ((l >> 3) & 1) * 8) * ROWB + (l >> 4) * 16);
    const uint32_t b_off = (uint32_t)(((l & 7) + (l >> 4) * 8) * ROWB + ((l >> 3) & 1) * 16);

    float acc[2][4][4];
#pragma unroll
    for (int mt = 0; mt < 2; mt++)
#pragma unroll
        for (int nt = 0; nt < 4; nt++)
#pragma unroll
            for (int i = 0; i < 4; i++) acc[mt][nt][i] = 0.0f;

    ld_stage_o(sb, A, W, bm, bn, 0, tid);
    ld_stage_o(sb, A, W, bm, bn, 1, tid);

#pragma unroll 1
    for (int kt = 0; kt < NKT; kt++) {
        if (kt < NKT - 2) asm volatile("cp.async.wait_group 1;" ::: "memory");
        else              asm volatile("cp.async.wait_group 0;" ::: "memory");
        __syncthreads();

        if (kt + 2 < NKT) ld_stage_o(sb, A, W, bm, bn, kt + 2, tid);

        const uint32_t As_u = sb + (uint32_t)((kt % GSTG) * OSTG_BYTES);
        const uint32_t Bs_u = As_u + OA_HALVES * 2;
        const uint32_t a_base = As_u + a_off + (uint32_t)(wm * 32 * ROWB);
        const uint32_t b_base = Bs_u + b_off + (uint32_t)(wn * 32 * ROWB);
#pragma unroll
        for (int ks = 0; ks < 4; ks++) {
            const uint32_t kb = ks * 32;
            uint32_t a[2][4], b[2][4];
#pragma unroll
            for (int mt = 0; mt < 2; mt++)
                ldsm_x4(a[mt], a_base + (uint32_t)(mt * 16 * ROWB) + kb);
            ldsm_x4(b[0], b_base + kb);
            ldsm_x4(b[1], b_base + (uint32_t)(16 * ROWB) + kb);
#pragma unroll
            for (int mt = 0; mt < 2; mt++)
#pragma unroll
                for (int nt = 0; nt < 4; nt++)
                    mma16(acc[mt][nt], a[mt], &b[nt >> 1][(nt & 1) * 2]);
        }
    }

    const int r_fr = l >> 2;
    const int c2 = (l & 3) * 2;
#pragma unroll
    for (int mt = 0; mt < 2; mt++) {
#pragma unroll
        for (int nt = 0; nt < 4; nt++) {
            int row = bm * OBM + wm * 32 + mt * 16 + r_fr;
            int col = bn * GBN + wn * 32 + nt * 8 + c2;
            float b0 = bias[col], b1 = bias[col + 1];
            *reinterpret_cast<float2*>(&C[(size_t)row * 512 + col]) =
                make_float2(acc[mt][nt][0] + b0, acc[mt][nt][1] + b1);
            *reinterpret_cast<float2*>(&C[(size_t)(row + 8) * 512 + col]) =
                make_float2(acc[mt][nt][2] + b0, acc[mt][nt][3] + b1);
        }
    }
}

// ---------------- fused scanA + scanB + aft (grid barriers, 256 blocks) ------------
#define FNB 256

__global__ void __launch_bounds__(256) fused_scan_aft_kernel() {
    __shared__ float2 s_ek[64 * 32];
    __shared__ float2 s_v [64 * 32];
    __shared__ float  s_epb[32 * 32];

    const int tid = threadIdx.x;
    const int blk = blockIdx.x;

    // ---- phase 1: scanA — ek = exp(k) (fp16), chunk partials ----
    {
        int chx = blk & 3, cy = blk >> 2;      // 4 x 64
        int ch = chx * 256 + tid;
        int t0 = cy * CHLEN;
        float sn = 0.f, sd = 0.f;
#pragma unroll 4
        for (int i = 0; i < CHLEN; i++) {
            int t = t0 + i;
            float e = __expf(g_k[(size_t)t * NCH + ch]);
            g_hek[(size_t)t * NCH + ch] = __float2half_rn(e);
            sd += e;
            sn += e * __half2float(g_hv[(size_t)t * NCH + ch]);
        }
        g_pden[ch * NCHUNK + cy] = sd;         // [ch][chunk]
        g_pnum[ch * NCHUNK + cy] = sn;
    }

    grid_barrier(&g_ctr0, &g_flag0, FNB);

    // ---- phase 2: scanB — warp-per-channel exclusive prefix (blocks 0..127) ----
    if (blk < 128) {
        const int ch   = (blk << 3) + (tid >> 5);
        const int lane = tid & 31;
        const float2* pn2 = reinterpret_cast<const float2*>(g_pnum + ch * NCHUNK);
        const float2* pd2 = reinterpret_cast<const float2*>(g_pden + ch * NCHUNK);
        float2 an = pn2[lane];
        float2 ad = pd2[lane];
        float ln = an.x + an.y;
        float ld = ad.x + ad.y;
        float sn = ln, sd = ld;
#pragma unroll
        for (int off = 1; off < 32; off <<= 1) {
            float tn = __shfl_up_sync(0xffffffff, sn, off);
            float td = __shfl_up_sync(0xffffffff, sd, off);
            if (lane >= off) { sn += tn; sd += td; }
        }
        float en = sn - ln, ed = sd - ld;
        g_pren[(2 * lane    ) * NCH + ch] = en;
        g_pren[(2 * lane + 1) * NCH + ch] = en + an.x;
        g_pred[(2 * lane    ) * NCH + ch] = ed;
        g_pred[(2 * lane + 1) * NCH + ch] = ed + ad.x;
    }

    grid_barrier(&g_ctr1, &g_flag1, FNB);

    // ---- phase 3: aft — 4 tiles per block (1024 tiles total) ----
    const int w = tid >> 5, l = tid & 31;
    const __half2* ek2 = reinterpret_cast<const __half2*>(g_hek);
    const __half2* v2g = reinterpret_cast<const __half2*>(g_hv);
    const __half2* q2g = reinterpret_cast<const __half2*>(g_hq);
    __half2* y2 = reinterpret_cast<__half2*>(g_hy);

#pragma unroll 1
    for (int it = 0; it < 4; it++) {
        const int tile = blk + it * FNB;       // 0..1023
        const int bx  = tile >> 4;             // 0..63
        const int chy = tile & 15;             // 0..15
        const int t0  = bx << 5;
        const int chp = chy * 32 + l;

        __syncthreads();                       // previous iteration's smem reads done
        for (int i = tid; i < 64 * 32; i += 256) {
            int r = i >> 5, cp = i & 31;
            int gr = t0 - 32 + r;
            float2 e = make_float2(0.f, 0.f), vv = make_float2(0.f, 0.f);
            if (gr >= 0) {
                size_t gi = (size_t)gr * 512 + chy * 32 + cp;
                e  = __half22float2(ek2[gi]);
                vv = __half22float2(v2g[gi]);
            }
            s_ek[i] = e; s_v[i] = vv;
        }
        for (int i = tid; i < 1024; i += 256)
            s_epb[i] = g_epb[t0 * 32 + i];
        __syncthreads();

        float rn_x = 0.f, rn_y = 0.f, rd_x = 0.f, rd_y = 0.f;
        if (bx > 0) {
            float2 pn = *reinterpret_cast<const float2*>(&g_pren[(size_t)(bx - 1) * NCH + 2 * chp]);
            float2 pd = *reinterpret_cast<const float2*>(&g_pred[(size_t)(bx - 1) * NCH + 2 * chp]);
            rn_x = pn.x; rn_y = pn.y; rd_x = pd.x; rd_y = pd.y;
        }

        float acc[4][4];
        for (int r = 0; r <= w; r++) {
            float2 e2 = s_ek[(r << 5) + l];
            float2 vv = s_v [(r << 5) + l];
            rn_x += e2.x * vv.x; rn_y += e2.y * vv.y;
            rd_x += e2.x;        rd_y += e2.y;
        }
        acc[0][0] = rn_x; acc[0][1] = rn_y; acc[0][2] = rd_x; acc[0][3] = rd_y;
#pragma unroll
        for (int ii = 1; ii < 4; ii++) {
            int rbase = w + (ii - 1) * 8 + 1;
#pragma unroll
            for (int rr = 0; rr < 8; rr++) {
                int r = rbase + rr;
                float2 e2 = s_ek[(r << 5) + l];
                float2 vv = s_v [(r << 5) + l];
                rn_x += e2.x * vv.x; rn_y += e2.y * vv.y;
                rd_x += e2.x;        rd_y += e2.y;
            }
            acc[ii][0] = rn_x; acc[ii][1] = rn_y; acc[ii][2] = rd_x; acc[ii][3] = rd_y;
        }

        const int ii_lo[7] = {0, 0, 0, 0, 1, 2, 3};
        const int ii_hi[7] = {0, 1, 2, 3, 3, 3, 3};
#pragma unroll
        for (int g = 0; g < 7; g++) {
#pragma unroll
            for (int rr = 0; rr < 8; rr++) {
                const int s = g * 8 + rr;
                const int row = w + 1 + s;
                float2 e2 = s_ek[(row << 5) + l];
                float2 vv = s_v [(row << 5) + l];
#pragma unroll
                for (int ii = ii_lo[g]; ii <= ii_hi[g]; ii++) {
                    const int tl = w + (ii << 3);
                    const int j  = s - (ii << 3);
                    float ep = s_epb[(tl << 5) + j];
                    float ex = e2.x * ep, ey = e2.y * ep;
                    acc[ii][0] += ex * vv.x; acc[ii][1] += ey * vv.y;
                    acc[ii][2] += ex;        acc[ii][3] += ey;
                }
            }
        }

#pragma unroll
        for (int ii = 0; ii < 4; ii++) {
            int t = t0 + w + (ii << 3);
            float2 q = __half22float2(q2g[(size_t)t * 512 + chp]);
            float sx = 1.f / (1.f + __expf(-q.x));
            float sy = 1.f / (1.f + __expf(-q.y));
            y2[(size_t)t * 512 + chp] =
                __floats2half2_rn(sx * acc[ii][0] / acc[ii][2], sy * acc[ii][1] / acc[ii][3]);
        }
    }

    // ---- cleanup: last block to finish resets barrier state for next graph replay ----
    __syncthreads();
    if (tid == 0) {
        __threadfence();
        unsigned v = atomicAdd(&g_done, 1);
        if (v == FNB - 1) {
            g_ctr0 = 0; g_flag0 = 0;
            g_ctr1 = 0; g_flag1 = 0;
            g_done = 0;
            __threadfence();
        }
    }
}

// ---------------- launch ----------------
extern "C" void kernel_launch(void* const* d_in, const int* in_sizes, int n_in,
                              void* d_out, int out_size) {
    const float* query = (const float*)d_in[0];
    const float* key   = (const float*)d_in[1];
    const float* value = (const float*)d_in[2];
    const float* Wq    = (const float*)d_in[3];
    const float* bq    = (const float*)d_in[4];
    const float* Wk    = (const float*)d_in[5];
    const float* bk    = (const float*)d_in[6];
    const float* Wv    = (const float*)d_in[7];
    const float* bv    = (const float*)d_in[8];
    const float* pb    = (const float*)d_in[9];
    const float* Wo    = (const float*)d_in[10];
    const float* bo    = (const float*)d_in[11];
    float* out = (float*)d_out;

    float *pk;
    __half *phq, *phv, *phx, *phw, *phy;
    cudaGetSymbolAddress((void**)&pk,  g_k);
    cudaGetSymbolAddress((void**)&phq, g_hq);
    cudaGetSymbolAddress((void**)&phv, g_hv);
    cudaGetSymbolAddress((void**)&phx, g_hx);
    cudaGetSymbolAddress((void**)&phw, g_hw);
    cudaGetSymbolAddress((void**)&phy, g_hy);

    cudaFuncSetAttribute(gemm_qkv, cudaFuncAttributeMaxDynamicSharedMemorySize, GEMM_SMEM);
    cudaFuncSetAttribute(gemm_o,   cudaFuncAttributeMaxDynamicSharedMemorySize, OGEMM_SMEM);

    // 1. fp16 rounding + epb table
    prep1_kernel<<<7424, 256>>>(pb, query, key, value, Wq, Wk, Wv, Wo);

    // 2. q/k/v projections (q,v -> fp16; k -> fp32)
    dim3 ggrid3(M_ROWS / GBM, D_MODEL / GBN, 3);   // (32, 4, 3)
    gemm_qkv<<<ggrid3, 256, GEMM_SMEM>>>(phx, phw, bq, bk, bv, phq, pk, phv);

    // 3. fused scanA + scanB + aft (grid barriers; writes fp16 y)
    fused_scan_aft_kernel<<<FNB, 256>>>();

    // 4. output projection
    dim3 ogrid(M_ROWS / OBM, D_MODEL / GBN);       // (64, 4)
    gemm_o<<<ogrid, 256, OGEMM_SMEM>>>(phy, phw + 3 * D_MODEL * D_MODEL, bo, out);
}

// round 15
// speedup vs baseline: 1.0884x; 1.0884x over previous
#include <cuda_runtime.h>
#include <cuda_fp16.h>
#include <cstdint>

// ---------------- problem constants ----------------
#define T_LEN   2048
#define BATCH   2
#define D_MODEL 512
#define S_WIN   32
#define M_ROWS  4096           // T*B
#define NCH     1024           // B*D channels

// ---------------- scratch (no allocation allowed) ----------------
__device__ float  g_k [M_ROWS * D_MODEL];          // k projection (fp32: exp-sensitive)
__device__ __half g_hq[M_ROWS * D_MODEL];          // q projection (fp16)
__device__ __half g_hv[M_ROWS * D_MODEL];          // v projection (fp16)
__device__ __half g_hek[M_ROWS * D_MODEL];         // exp(k) (fp16)
__device__ __half g_hx[3 * M_ROWS * D_MODEL];      // fp16 rounded query,key,value
__device__ __half g_hw[4 * D_MODEL * D_MODEL];     // fp16 rounded Wq,Wk,Wv,Wo
__device__ __half g_hy[M_ROWS * D_MODEL];          // fp16 y (gemm_o input)
__device__ float g_epb[T_LEN * S_WIN];

#define NCHUNK 64
#define CHLEN  32              // == S_WIN (prefix-in-block trick relies on this)
__device__ float g_pnum[NCH * NCHUNK];   // raw partials, [ch][chunk]
__device__ float g_pden[NCH * NCHUNK];
__device__ float g_pren[NCHUNK * NCH];   // exclusive prefix, [chunk][ch]
__device__ float g_pred[NCHUNK * NCH];

// ---------------- helpers ----------------
__device__ __forceinline__ void mma16(float c[4], const uint32_t a[4], const uint32_t b[2]) {
    asm volatile(
        "mma.sync.aligned.m16n8k16.row.col.f32.f16.f16.f32 "
        "{%0,%1,%2,%3}, {%4,%5,%6,%7}, {%8,%9}, {%0,%1,%2,%3};\n"
        : "+f"(c[0]), "+f"(c[1]), "+f"(c[2]), "+f"(c[3])
        : "r"(a[0]), "r"(a[1]), "r"(a[2]), "r"(a[3]),
          "r"(b[0]), "r"(b[1]));
}
__device__ __forceinline__ void ldsm_x4(uint32_t r[4], uint32_t addr) {
    asm volatile("ldmatrix.sync.aligned.m8n8.x4.shared.b16 {%0,%1,%2,%3}, [%4];"
        : "=r"(r[0]), "=r"(r[1]), "=r"(r[2]), "=r"(r[3]) : "r"(addr));
}
__device__ __forceinline__ void cp16(uint32_t dst, const void* src) {
    asm volatile("cp.async.cg.shared.global [%0], [%1], 16;" :: "r"(dst), "l"(src));
}
__device__ __forceinline__ void cp_commit() {
    asm volatile("cp.async.commit_group;" ::: "memory");
}
__device__ __forceinline__ uint32_t smem_to_u32(const void* p) {
    uint32_t a;
    asm("{ .reg .u64 t; cvta.to.shared.u64 t, %1; cvt.u32.u64 %0, t; }" : "=r"(a) : "l"(p));
    return a;
}
__device__ __forceinline__ uint32_t pack_h2(float a, float b) {
    __half2 h = __floats2half2_rn(a, b);
    return *reinterpret_cast<uint32_t*>(&h);
}

// ---------------- prep1: fp16 conversion + exp(pb) window table ----------------
__global__ __launch_bounds__(256) void prep1_kernel(
    const float* __restrict__ pb,
    const float* __restrict__ query, const float* __restrict__ key, const float* __restrict__ value,
    const float* __restrict__ Wq, const float* __restrict__ Wk, const float* __restrict__ Wv,
    const float* __restrict__ Wo)
{
    int blk = blockIdx.x;
    if (blk >= 7168) {
        int id = (blk - 7168) * 256 + threadIdx.x;
        int t = id >> 5, j = id & 31;
        int idx = t - (S_WIN - 1) + j;
        g_epb[id] = (idx >= 0) ? __expf(pb[(size_t)t * T_LEN + idx]) : 0.0f;
        return;
    }
    int i = blk * 256 + threadIdx.x;   // float4 index
    const float4* src;
    __half* dstbase;
    int j;
    if (i < 524288)       { src = (const float4*)query; dstbase = g_hx;           j = i; }
    else if (i < 1048576) { src = (const float4*)key;   dstbase = g_hx + 2097152; j = i - 524288; }
    else if (i < 1572864) { src = (const float4*)value; dstbase = g_hx + 4194304; j = i - 1048576; }
    else if (i < 1638400) { src = (const float4*)Wq;    dstbase = g_hw;           j = i - 1572864; }
    else if (i < 1703936) { src = (const float4*)Wk;    dstbase = g_hw + 262144;  j = i - 1638400; }
    else if (i < 1769472) { src = (const float4*)Wv;    dstbase = g_hw + 524288;  j = i - 1703936; }
    else                  { src = (const float4*)Wo;    dstbase = g_hw + 786432;  j = i - 1769472; }
    float4 v = src[j];
    uint2 h;
    h.x = pack_h2(v.x, v.y);
    h.y = pack_h2(v.z, v.w);
    *reinterpret_cast<uint2*>(dstbase + (size_t)j * 4) = h;
}

// ---------------- fp16 pipelined GEMM ----------------
// z=0 -> q as fp16, z=1 -> k as fp32, z=2 -> v as fp16
#define GBM 128
#define GBN 128
#define GBK 64
#define GSTG 3
#define NKT 8
#define PADH 72
#define ROWB 144
#define A_HALVES (GBM * PADH)
#define STG_HALVES (2 * A_HALVES)
#define STG_BYTES (STG_HALVES * 2)
#define GEMM_SMEM (GSTG * STG_BYTES)

__device__ __forceinline__ void ld_stage(uint32_t sb, const __half* __restrict__ A,
                                         const __half* __restrict__ W,
                                         int bm, int bn, int kt, int tid) {
    uint32_t base = sb + (uint32_t)((kt % GSTG) * STG_BYTES);
#pragma unroll
    for (int i = 0; i < 4; i++) {
        int chunk = tid + i * 256;
        int row = chunk >> 3, c16 = chunk & 7;
        cp16(base + (uint32_t)(row * ROWB + c16 * 16),
             &A[(size_t)(bm * GBM + row) * 512 + kt * GBK + c16 * 8]);
    }
    base += A_HALVES * 2;
#pragma unroll
    for (int i = 0; i < 4; i++) {
        int chunk = tid + i * 256;
        int row = chunk >> 3, c16 = chunk & 7;
        cp16(base + (uint32_t)(row * ROWB + c16 * 16),
             &W[(size_t)(bn * GBN + row) * 512 + kt * GBK + c16 * 8]);
    }
    cp_commit();
}

__global__ void __launch_bounds__(256, 2) gemm_qkv(
    const __half* __restrict__ X, const __half* __restrict__ Wh,
    const float* __restrict__ B0, const float* __restrict__ B1, const float* __restrict__ B2,
    __half* __restrict__ Cq, float* __restrict__ Ck, __half* __restrict__ Cv)
{
    extern __shared__ char smem_c[];
    const uint32_t sb = smem_to_u32(smem_c);
    const int tid  = threadIdx.x;
    const int l    = tid & 31;
    const int wid  = tid >> 5;
    const int wm   = wid & 1;
    const int wn   = wid >> 1;
    const int bm   = blockIdx.x, bn = blockIdx.y;
    const int z    = blockIdx.z;

    const __half* A    = X  + (size_t)z * (M_ROWS * D_MODEL);
    const __half* W    = Wh + (size_t)z * (D_MODEL * D_MODEL);
    const float* bias  = (z == 0) ? B0 : (z == 1) ? B1 : B2;

    const uint32_t a_off = (uint32_t)(((l & 7) + ((l >> 3) & 1) * 8) * ROWB + (l >> 4) * 16);
    const uint32_t b_off = (uint32_t)(((l & 7) + (l >> 4) * 8) * ROWB + ((l >> 3) & 1) * 16);

    float acc[4][4][4];
#pragma unroll
    for (int mt = 0; mt < 4; mt++)
#pragma unroll
        for (int nt = 0; nt < 4; nt++)
#pragma unroll
            for (int i = 0; i < 4; i++) acc[mt][nt][i] = 0.0f;

    ld_stage(sb, A, W, bm, bn, 0, tid);
    ld_stage(sb, A, W, bm, bn, 1, tid);

#pragma unroll 1
    for (int kt = 0; kt < NKT; kt++) {
        if (kt < NKT - 2) asm volatile("cp.async.wait_group 1;" ::: "memory");
        else              asm volatile("cp.async.wait_group 0;" ::: "memory");
        __syncthreads();

        if (kt + 2 < NKT) ld_stage(sb, A, W, bm, bn, kt + 2, tid);

        const uint32_t As_u = sb + (uint32_t)((kt % GSTG) * STG_BYTES);
        const uint32_t Bs_u = As_u + A_HALVES * 2;
        const uint32_t a_base = As_u + a_off + (uint32_t)(wm * 64 * ROWB);
        const uint32_t b_base = Bs_u + b_off + (uint32_t)(wn * 32 * ROWB);
#pragma unroll
        for (int ks = 0; ks < 4; ks++) {
            const uint32_t kb = ks * 32;
            uint32_t a[4][4], b[2][4];
#pragma unroll
            for (int mt = 0; mt < 4; mt++)
                ldsm_x4(a[mt], a_base + (uint32_t)(mt * 16 * ROWB) + kb);
            ldsm_x4(b[0], b_base + kb);
            ldsm_x4(b[1], b_base + (uint32_t)(16 * ROWB) + kb);
#pragma unroll
            for (int mt = 0; mt < 4; mt++)
#pragma unroll
                for (int nt = 0; nt < 4; nt++)
                    mma16(acc[mt][nt], a[mt], &b[nt >> 1][(nt & 1) * 2]);
        }
    }

    const int r_fr = l >> 2;
    const int c2 = (l & 3) * 2;
    if (z == 1) {
#pragma unroll
        for (int mt = 0; mt < 4; mt++) {
#pragma unroll
            for (int nt = 0; nt < 4; nt++) {
                int row = bm * GBM + wm * 64 + mt * 16 + r_fr;
                int col = bn * GBN + wn * 32 + nt * 8 + c2;
                float b0 = bias[col], b1 = bias[col + 1];
                *reinterpret_cast<float2*>(&Ck[(size_t)row * 512 + col]) =
                    make_float2(acc[mt][nt][0] + b0, acc[mt][nt][1] + b1);
                *reinterpret_cast<float2*>(&Ck[(size_t)(row + 8) * 512 + col]) =
                    make_float2(acc[mt][nt][2] + b0, acc[mt][nt][3] + b1);
            }
        }
    } else {
        __half* Ch = (z == 0) ? Cq : Cv;
#pragma unroll
        for (int mt = 0; mt < 4; mt++) {
#pragma unroll
            for (int nt = 0; nt < 4; nt++) {
                int row = bm * GBM + wm * 64 + mt * 16 + r_fr;
                int col = bn * GBN + wn * 32 + nt * 8 + c2;
                float b0 = bias[col], b1 = bias[col + 1];
                *reinterpret_cast<__half2*>(&Ch[(size_t)row * 512 + col]) =
                    __floats2half2_rn(acc[mt][nt][0] + b0, acc[mt][nt][1] + b1);
                *reinterpret_cast<__half2*>(&Ch[(size_t)(row + 8) * 512 + col]) =
                    __floats2half2_rn(acc[mt][nt][2] + b0, acc[mt][nt][3] + b1);
            }
        }
    }
}

// ---------------- gemm_o: BM=64, BN=128, 2-stage, 3 CTAs/SM -------------------------
#define OBM 64
#define OSTG 2
#define OA_HALVES (OBM * PADH)
#define OSTG_HALVES (OA_HALVES + A_HALVES)
#define OSTG_BYTES (OSTG_HALVES * 2)           // 27,648 B
#define OGEMM_SMEM (OSTG * OSTG_BYTES)         // 55,296 B -> 3 CTAs/SM

__device__ __forceinline__ void ld_stage_o(uint32_t sb, const __half* __restrict__ A,
                                           const __half* __restrict__ W,
                                           int bm, int bn, int kt, int tid) {
    uint32_t base = sb + (uint32_t)((kt & 1) * OSTG_BYTES);
#pragma unroll
    for (int i = 0; i < 2; i++) {
        int chunk = tid + i * 256;             // 512 chunks: 64 rows x 8
        int row = chunk >> 3, c16 = chunk & 7;
        cp16(base + (uint32_t)(row * ROWB + c16 * 16),
             &A[(size_t)(bm * OBM + row) * 512 + kt * GBK + c16 * 8]);
    }
    base += OA_HALVES * 2;
#pragma unroll
    for (int i = 0; i < 4; i++) {
        int chunk = tid + i * 256;             // 1024 chunks: 128 rows x 8
        int row = chunk >> 3, c16 = chunk & 7;
        cp16(base + (uint32_t)(row * ROWB + c16 * 16),
             &W[(size_t)(bn * GBN + row) * 512 + kt * GBK + c16 * 8]);
    }
    cp_commit();
}

__global__ void __launch_bounds__(256, 3) gemm_o(
    const __half* __restrict__ A, const __half* __restrict__ W,
    const float* __restrict__ bias, float* __restrict__ C)
{
    extern __shared__ char smem_c[];
    const uint32_t sb = smem_to_u32(smem_c);
    const int tid  = threadIdx.x;
    const int l    = tid & 31;
    const int wid  = tid >> 5;
    const int wm   = wid & 1;        // 2 warps in m
    const int wn   = wid >> 1;       // 4 warps in n
    const int bm   = blockIdx.x, bn = blockIdx.y;

    const uint32_t a_off = (uint32_t)(((l & 7) + ((l >> 3) & 1) * 8) * ROWB + (l >> 4) * 16);
    const uint32_t b_off = (uint32_t)(((l & 7) + (l >> 4) * 8) * ROWB + ((l >> 3) & 1) * 16);

    float acc[2][4][4];
#pragma unroll
    for (int mt = 0; mt < 2; mt++)
#pragma unroll
        for (int nt = 0; nt < 4; nt++)
#pragma unroll
            for (int i = 0; i < 4; i++) acc[mt][nt][i] = 0.0f;

    ld_stage_o(sb, A, W, bm, bn, 0, tid);

#pragma unroll 1
    for (int kt = 0; kt < NKT; kt++) {
        if (kt + 1 < NKT) {
            ld_stage_o(sb, A, W, bm, bn, kt + 1, tid);
            asm volatile("cp.async.wait_group 1;" ::: "memory");   // stage kt ready
        } else {
            asm volatile("cp.async.wait_group 0;" ::: "memory");
        }
        __syncthreads();

        const uint32_t As_u = sb + (uint32_t)((kt & 1) * OSTG_BYTES);
        const uint32_t Bs_u = As_u + OA_HALVES * 2;
        const uint32_t a_base = As_u + a_off + (uint32_t)(wm * 32 * ROWB);
        const uint32_t b_base = Bs_u + b_off + (uint32_t)(wn * 32 * ROWB);
#pragma unroll
        for (int ks = 0; ks < 4; ks++) {
            const uint32_t kb = ks * 32;
            uint32_t a[2][4], b[2][4];
#pragma unroll
            for (int mt = 0; mt < 2; mt++)
                ldsm_x4(a[mt], a_base + (uint32_t)(mt * 16 * ROWB) + kb);
            ldsm_x4(b[0], b_base + kb);
            ldsm_x4(b[1], b_base + (uint32_t)(16 * ROWB) + kb);
#pragma unroll
            for (int mt = 0; mt < 2; mt++)
#pragma unroll
                for (int nt = 0; nt < 4; nt++)
                    mma16(acc[mt][nt], a[mt], &b[nt >> 1][(nt & 1) * 2]);
        }
        __syncthreads();   // reads done before next iter's ld overwrites buffer kt&1
    }

    const int r_fr = l >> 2;
    const int c2 = (l & 3) * 2;
#pragma unroll
    for (int mt = 0; mt < 2; mt++) {
#pragma unroll
        for (int nt = 0; nt < 4; nt++) {
            int row = bm * OBM + wm * 32 + mt * 16 + r_fr;
            int col = bn * GBN + wn * 32 + nt * 8 + c2;
            float b0 = bias[col], b1 = bias[col + 1];
            *reinterpret_cast<float2*>(&C[(size_t)row * 512 + col]) =
                make_float2(acc[mt][nt][0] + b0, acc[mt][nt][1] + b1);
            *reinterpret_cast<float2*>(&C[(size_t)(row + 8) * 512 + col]) =
                make_float2(acc[mt][nt][2] + b0, acc[mt][nt][3] + b1);
        }
    }
}

// ---------------- scanA: ek = exp(k) (fp16 out), chunk partials ----------------
__global__ void scanA_kernel() {
    int ch = blockIdx.x * 256 + threadIdx.x;   // gridDim.x = 4
    int t0 = blockIdx.y * CHLEN;               // gridDim.y = 64
    float sn = 0.f, sd = 0.f;
#pragma unroll 4
    for (int i = 0; i < CHLEN; i++) {
        int t = t0 + i;
        float e = __expf(g_k[(size_t)t * NCH + ch]);
        g_hek[(size_t)t * NCH + ch] = __float2half_rn(e);
        sd += e;
        sn += e * __half2float(g_hv[(size_t)t * NCH + ch]);
    }
    g_pden[ch * NCHUNK + blockIdx.y] = sd;     // [ch][chunk]
    g_pnum[ch * NCHUNK + blockIdx.y] = sn;
}

// ---------------- scanB: warp-per-channel exclusive prefix -> transposed out --------
__global__ void scanB_kernel() {
    const int ch   = (blockIdx.x << 3) + (threadIdx.x >> 5);   // 128 blocks x 8 warps
    const int lane = threadIdx.x & 31;
    const float2* pn2 = reinterpret_cast<const float2*>(g_pnum + ch * NCHUNK);
    const float2* pd2 = reinterpret_cast<const float2*>(g_pden + ch * NCHUNK);
    float2 an = pn2[lane];
    float2 ad = pd2[lane];
    float ln = an.x + an.y;
    float ld = ad.x + ad.y;
    float sn = ln, sd = ld;
#pragma unroll
    for (int off = 1; off < 32; off <<= 1) {
        float tn = __shfl_up_sync(0xffffffff, sn, off);
        float td = __shfl_up_sync(0xffffffff, sd, off);
        if (lane >= off) { sn += tn; sd += td; }
    }
    float en = sn - ln, ed = sd - ld;          // exclusive at chunk 2*lane
    g_pren[(2 * lane    ) * NCH + ch] = en;
    g_pren[(2 * lane + 1) * NCH + ch] = en + an.x;
    g_pred[(2 * lane    ) * NCH + ch] = ed;
    g_pred[(2 * lane + 1) * NCH + ch] = ed + ad.x;
}

// ---------------- AFT: window + in-block prefix + gating -------------------------
__global__ __launch_bounds__(256) void aft_kernel() {
    __shared__ float2 s_ek[64 * 32];
    __shared__ float2 s_v [64 * 32];
    __shared__ float  s_epb[32 * 32];

    const int tid = threadIdx.x;
    const int w = tid >> 5, l = tid & 31;
    const int bx = blockIdx.x;                 // 64 blocks
    const int t0 = bx << 5;
    const int chp = blockIdx.y * 32 + l;       // half2 channel index (0..511)

    const __half2* ek2 = reinterpret_cast<const __half2*>(g_hek);
    const __half2* v2g = reinterpret_cast<const __half2*>(g_hv);

    for (int i = tid; i < 64 * 32; i += 256) {
        int r = i >> 5, cp = i & 31;
        int gr = t0 - 32 + r;
        float2 e = make_float2(0.f, 0.f), vv = make_float2(0.f, 0.f);
        if (gr >= 0) {
            size_t gi = (size_t)gr * 512 + blockIdx.y * 32 + cp;
            e  = __half22float2(ek2[gi]);
            vv = __half22float2(v2g[gi]);
        }
        s_ek[i] = e; s_v[i] = vv;
    }
    for (int i = tid; i < 1024; i += 256)
        s_epb[i] = g_epb[t0 * 32 + i];
    __syncthreads();

    const __half2* q2g = reinterpret_cast<const __half2*>(g_hq);
    __half2* y2 = reinterpret_cast<__half2*>(g_hy);

    // running prefix starting at chunk-exclusive offset (zero for bx==0) — coalesced
    float rn_x = 0.f, rn_y = 0.f, rd_x = 0.f, rd_y = 0.f;
    if (bx > 0) {
        float2 pn = *reinterpret_cast<const float2*>(&g_pren[(size_t)(bx - 1) * NCH + 2 * chp]);
        float2 pd = *reinterpret_cast<const float2*>(&g_pred[(size_t)(bx - 1) * NCH + 2 * chp]);
        rn_x = pn.x; rn_y = pn.y; rd_x = pd.x; rd_y = pd.y;
    }

    float acc[4][4];     // [ii][nx, ny, dx, dy]
    for (int r = 0; r <= w; r++) {
        float2 e2 = s_ek[(r << 5) + l];
        float2 vv = s_v [(r << 5) + l];
        rn_x += e2.x * vv.x; rn_y += e2.y * vv.y;
        rd_x += e2.x;        rd_y += e2.y;
    }
    acc[0][0] = rn_x; acc[0][1] = rn_y; acc[0][2] = rd_x; acc[0][3] = rd_y;
#pragma unroll
    for (int ii = 1; ii < 4; ii++) {
        int rbase = w + (ii - 1) * 8 + 1;
#pragma unroll
        for (int rr = 0; rr < 8; rr++) {
            int r = rbase + rr;
            float2 e2 = s_ek[(r << 5) + l];
            float2 vv = s_v [(r << 5) + l];
            rn_x += e2.x * vv.x; rn_y += e2.y * vv.y;
            rd_x += e2.x;        rd_y += e2.y;
        }
        acc[ii][0] = rn_x; acc[ii][1] = rn_y; acc[ii][2] = rd_x; acc[ii][3] = rd_y;
    }

    const int ii_lo[7] = {0, 0, 0, 0, 1, 2, 3};
    const int ii_hi[7] = {0, 1, 2, 3, 3, 3, 3};
#pragma unroll
    for (int g = 0; g < 7; g++) {
#pragma unroll
        for (int rr = 0; rr < 8; rr++) {
            const int s = g * 8 + rr;
            const int row = w + 1 + s;         // 1..63
            float2 e2 = s_ek[(row << 5) + l];
            float2 vv = s_v [(row << 5) + l];
#pragma unroll
            for (int ii = ii_lo[g]; ii <= ii_hi[g]; ii++) {
                const int tl = w + (ii << 3);
                const int j  = s - (ii << 3);
                float ep = s_epb[(tl << 5) + j];
                float ex = e2.x * ep, ey = e2.y * ep;
                acc[ii][0] += ex * vv.x; acc[ii][1] += ey * vv.y;
                acc[ii][2] += ex;        acc[ii][3] += ey;
            }
        }
    }

#pragma unroll
    for (int ii = 0; ii < 4; ii++) {
        int t = t0 + w + (ii << 3);
        float2 q = __half22float2(q2g[(size_t)t * 512 + chp]);
        float sx = 1.f / (1.f + __expf(-q.x));
        float sy = 1.f / (1.f + __expf(-q.y));
        y2[(size_t)t * 512 + chp] =
            __floats2half2_rn(sx * acc[ii][0] / acc[ii][2], sy * acc[ii][1] / acc[ii][3]);
    }
}

// ---------------- launch ----------------
extern "C" void kernel_launch(void* const* d_in, const int* in_sizes, int n_in,
                              void* d_out, int out_size) {
    const float* query = (const float*)d_in[0];
    const float* key   = (const float*)d_in[1];
    const float* value = (const float*)d_in[2];
    const float* Wq    = (const float*)d_in[3];
    const float* bq    = (const float*)d_in[4];
    const float* Wk    = (const float*)d_in[5];
    const float* bk    = (const float*)d_in[6];
    const float* Wv    = (const float*)d_in[7];
    const float* bv    = (const float*)d_in[8];
    const float* pb    = (const float*)d_in[9];
    const float* Wo    = (const float*)d_in[10];
    const float* bo    = (const float*)d_in[11];
    float* out = (float*)d_out;

    float *pk;
    __half *phq, *phv, *phx, *phw, *phy;
    cudaGetSymbolAddress((void**)&pk,  g_k);
    cudaGetSymbolAddress((void**)&phq, g_hq);
    cudaGetSymbolAddress((void**)&phv, g_hv);
    cudaGetSymbolAddress((void**)&phx, g_hx);
    cudaGetSymbolAddress((void**)&phw, g_hw);
    cudaGetSymbolAddress((void**)&phy, g_hy);

    cudaFuncSetAttribute(gemm_qkv, cudaFuncAttributeMaxDynamicSharedMemorySize, GEMM_SMEM);
    cudaFuncSetAttribute(gemm_o,   cudaFuncAttributeMaxDynamicSharedMemorySize, OGEMM_SMEM);

    // 1. fp16 rounding + epb table
    prep1_kernel<<<7424, 256>>>(pb, query, key, value, Wq, Wk, Wv, Wo);

    // 2. q/k/v projections (q,v -> fp16; k -> fp32)
    dim3 ggrid3(M_ROWS / GBM, D_MODEL / GBN, 3);   // (32, 4, 3)
    gemm_qkv<<<ggrid3, 256, GEMM_SMEM>>>(phx, phw, bq, bk, bv, phq, pk, phv);

    // 3. ek (fp16) + chunk partials, 4. exclusive chunk prefix (transposed)
    scanA_kernel<<<dim3(4, NCHUNK), 256>>>();
    scanB_kernel<<<128, 256>>>();

    // 5. AFT window + in-block prefix + gating (writes fp16 y)
    aft_kernel<<<dim3(64, 16), 256>>>();

    // 6. output projection (2-stage, 3 CTAs/SM)
    dim3 ogrid(M_ROWS / OBM, D_MODEL / GBN);       // (64, 4)
    gemm_o<<<ogrid, 256, OGEMM_SMEM>>>(phy, phw + 3 * D_MODEL * D_MODEL, bo, out);
}